// round 1
// baseline (speedup 1.0000x reference)
#include <cuda_runtime.h>
#include <cstddef>

#define N_NODES 50000
#define HID 64

// ---------------- scratch (device globals: no allocation allowed) ----------------
__device__ __align__(256) float g_deg[N_NODES];          // degree -> 1/max(deg,1)
__device__ __align__(256) float g_P[N_NODES * 64];       // neighbor projection h @ Wl^T
__device__ __align__(256) float g_R[N_NODES * 64];       // root projection     h @ Wr^T
__device__ __align__(256) float g_S[N_NODES * 64];       // scatter accumulator
__device__ __align__(256) float g_H[N_NODES * 192];      // x_cat = [h0 | h1 | h2]
__device__ __align__(256) float g_U[N_NODES * 64];       // x_cat @ W1a^T
__device__ __align__(256) float g_V[N_NODES * 64];       // x_cat @ W1b^T

// ---------------- utility kernels ----------------
__global__ void zero_kernel(float4* __restrict__ p, int n4) {
    int i = blockIdx.x * blockDim.x + threadIdx.x;
    if (i < n4) p[i] = make_float4(0.f, 0.f, 0.f, 0.f);
}

__global__ void count_deg_kernel(const int* __restrict__ dst, float* __restrict__ deg, int E) {
    int e = blockIdx.x * blockDim.x + threadIdx.x;
    if (e < E) atomicAdd(&deg[dst[e]], 1.0f);
}

__global__ void inv_deg_kernel(float* __restrict__ deg, int n) {
    int i = blockIdx.x * blockDim.x + threadIdx.x;
    if (i < n) deg[i] = 1.0f / fmaxf(deg[i], 1.0f);
}

// ---------------- dual-output GEMM ----------------
// Computes, for 64-node tiles:
//   Ot[n, 0:64] = A[n, :K] @ Wt[0:64, :K]^T
//   Ob[n, 0:64] = A[n, :K] @ Wb[0:64, :K]^T
// A row stride = lda, W row stride = wld. K must be a multiple of 32.
#define GEMM_BK 32
__global__ __launch_bounds__(256) void gemm_dual(
    const float* __restrict__ A, int lda, int K,
    const float* __restrict__ Wt, const float* __restrict__ Wb, int wld,
    float* __restrict__ Ot, float* __restrict__ Ob, int nNodes)
{
    __shared__ float Ash[GEMM_BK][68];    // [k][node], padded (16B-aligned rows)
    __shared__ float Wsh[GEMM_BK][132];   // [k][out],  padded (16B-aligned rows)

    const int t  = threadIdx.x;           // 256 threads
    const int gi = t >> 4;                // node group 0..15  (4 nodes each)
    const int gj = t & 15;                // out  group 0..15  (8 outs each)
    const int n0 = blockIdx.x * 64;

    float acc[4][8];
#pragma unroll
    for (int i = 0; i < 4; i++)
#pragma unroll
        for (int j = 0; j < 8; j++) acc[i][j] = 0.f;

    for (int k0 = 0; k0 < K; k0 += GEMM_BK) {
        // load A chunk (64 x 32), transposed into smem
        for (int idx = t; idx < 64 * GEMM_BK; idx += 256) {
            int n = idx >> 5;
            int k = idx & 31;
            float v = 0.f;
            if (n0 + n < nNodes) v = A[(size_t)(n0 + n) * lda + k0 + k];
            Ash[k][n] = v;
        }
        // load W chunk (128 x 32), transposed into smem; o<64 -> Wt, else Wb
        for (int idx = t; idx < 128 * GEMM_BK; idx += 256) {
            int o = idx >> 5;
            int k = idx & 31;
            const float* wr = (o < 64) ? (Wt + (size_t)o * wld)
                                       : (Wb + (size_t)(o - 64) * wld);
            Wsh[k][o] = wr[k0 + k];
        }
        __syncthreads();
#pragma unroll
        for (int k = 0; k < GEMM_BK; k++) {
            const float4 a4  = *(const float4*)&Ash[k][gi * 4];
            const float4 w04 = *(const float4*)&Wsh[k][gj * 8];
            const float4 w14 = *(const float4*)&Wsh[k][gj * 8 + 4];
            const float av[4] = {a4.x, a4.y, a4.z, a4.w};
            const float wv[8] = {w04.x, w04.y, w04.z, w04.w,
                                 w14.x, w14.y, w14.z, w14.w};
#pragma unroll
            for (int i = 0; i < 4; i++)
#pragma unroll
                for (int j = 0; j < 8; j++)
                    acc[i][j] += av[i] * wv[j];
        }
        __syncthreads();
    }

    float* O = (gj < 8) ? Ot : Ob;
    const int o = (gj & 7) * 8;
#pragma unroll
    for (int i = 0; i < 4; i++) {
        int n = n0 + gi * 4 + i;
        if (n < nNodes) {
            float4 r0 = make_float4(acc[i][0], acc[i][1], acc[i][2], acc[i][3]);
            float4 r1 = make_float4(acc[i][4], acc[i][5], acc[i][6], acc[i][7]);
            *(float4*)(O + (size_t)n * 64 + o)     = r0;
            *(float4*)(O + (size_t)n * 64 + o + 4) = r1;
        }
    }
}

// ---------------- scatter: S[dst] += P[src], 64 floats/edge ----------------
// 4 threads per edge; vectorized red.global.add.v4.f32 (sm_90+).
__global__ __launch_bounds__(256) void scatter_kernel(
    const float* __restrict__ P, const int* __restrict__ src,
    const int* __restrict__ dst, float* __restrict__ S, int E)
{
    int tid = blockIdx.x * blockDim.x + threadIdx.x;
    if (tid >= E * 4) return;
    int e = tid >> 2;
    int q = tid & 3;
    int s = __ldg(src + e);
    int d = __ldg(dst + e);
    const float4* p = (const float4*)(P + (size_t)s * 64) + q * 4;
    float* ob = S + (size_t)d * 64 + q * 16;
#pragma unroll
    for (int j = 0; j < 4; j++) {
        float4 v = __ldg(p + j);
        asm volatile("red.global.add.v4.f32 [%0], {%1, %2, %3, %4};"
                     :: "l"(ob + j * 4), "f"(v.x), "f"(v.y), "f"(v.z), "f"(v.w)
                     : "memory");
    }
}

// ---------------- combine: h = relu(S * deg_inv + bl + R), write into H column band ----------------
__global__ __launch_bounds__(256) void combine_kernel(
    const float* __restrict__ S, const float* __restrict__ R,
    const float* __restrict__ deginv, const float* __restrict__ bl,
    float* __restrict__ H, int col, int n)
{
    int tid = blockIdx.x * blockDim.x + threadIdx.x;
    if (tid >= n * 16) return;
    int nn = tid >> 4;
    int j  = tid & 15;
    float di = deginv[nn];
    float4 s = *(const float4*)(S + (size_t)nn * 64 + j * 4);
    float4 r = *(const float4*)(R + (size_t)nn * 64 + j * 4);
    float4 b = *(const float4*)(bl + j * 4);
    float4 h;
    h.x = fmaxf(fmaf(s.x, di, b.x) + r.x, 0.f);
    h.y = fmaxf(fmaf(s.y, di, b.y) + r.y, 0.f);
    h.z = fmaxf(fmaf(s.z, di, b.z) + r.z, 0.f);
    h.w = fmaxf(fmaf(s.w, di, b.w) + r.w, 0.f);
    *(float4*)(H + (size_t)nn * 192 + col + j * 4) = h;
}

// ---------------- edge head: out[e] = relu(U[src] + V[dst] + bm1) . wm2 + bm2 ----------------
__global__ __launch_bounds__(256) void edge_kernel(
    const float* __restrict__ U, const float* __restrict__ V,
    const int* __restrict__ src, const int* __restrict__ dst,
    const float* __restrict__ bm1, const float* __restrict__ Wm2,
    const float* __restrict__ bm2, float* __restrict__ out, int E)
{
    __shared__ float bsh[64];
    __shared__ float wsh[64];
    int t = threadIdx.x;
    if (t < 64)       bsh[t]      = bm1[t];
    else if (t < 128) wsh[t - 64] = Wm2[t - 64];
    __syncthreads();

    int e = blockIdx.x * blockDim.x + t;
    if (e >= E) return;
    int s = __ldg(src + e);
    int d = __ldg(dst + e);
    const float4* up = (const float4*)(U + (size_t)s * 64);
    const float4* vp = (const float4*)(V + (size_t)d * 64);
    float acc = __ldg(bm2);
#pragma unroll 4
    for (int j = 0; j < 16; j++) {
        float4 u = __ldg(up + j);
        float4 v = __ldg(vp + j);
        float4 b = *(const float4*)&bsh[j * 4];
        float4 w = *(const float4*)&wsh[j * 4];
        acc += fmaxf(u.x + v.x + b.x, 0.f) * w.x;
        acc += fmaxf(u.y + v.y + b.y, 0.f) * w.y;
        acc += fmaxf(u.z + v.z + b.z, 0.f) * w.z;
        acc += fmaxf(u.w + v.w + b.w, 0.f) * w.w;
    }
    out[e] = acc;
}

// ---------------- host launcher ----------------
extern "C" void kernel_launch(void* const* d_in, const int* in_sizes, int n_in,
                              void* d_out, int out_size)
{
    const float* x   = (const float*)d_in[0];
    const int*   src = (const int*)d_in[1];
    const int*   dst = (const int*)d_in[2];
    const float* Wl0 = (const float*)d_in[3];
    const float* bl0 = (const float*)d_in[4];
    const float* Wr0 = (const float*)d_in[5];
    const float* Wl1 = (const float*)d_in[6];
    const float* bl1 = (const float*)d_in[7];
    const float* Wr1 = (const float*)d_in[8];
    const float* Wl2 = (const float*)d_in[9];
    const float* bl2 = (const float*)d_in[10];
    const float* Wr2 = (const float*)d_in[11];
    const float* Wm1 = (const float*)d_in[12];
    const float* bm1 = (const float*)d_in[13];
    const float* Wm2 = (const float*)d_in[14];
    const float* bm2 = (const float*)d_in[15];
    float* out = (float*)d_out;
    const int E = in_sizes[1];

    void* p;
    cudaGetSymbolAddress(&p, g_deg); float* deg = (float*)p;
    cudaGetSymbolAddress(&p, g_P);   float* P   = (float*)p;
    cudaGetSymbolAddress(&p, g_R);   float* R   = (float*)p;
    cudaGetSymbolAddress(&p, g_S);   float* S   = (float*)p;
    cudaGetSymbolAddress(&p, g_H);   float* H   = (float*)p;
    cudaGetSymbolAddress(&p, g_U);   float* U   = (float*)p;
    cudaGetSymbolAddress(&p, g_V);   float* V   = (float*)p;

    const int T = 256;
    const int gemm_blocks = (N_NODES + 63) / 64;

    // degree (reused by all 3 layers)
    zero_kernel<<<(N_NODES / 4 + T - 1) / T, T>>>((float4*)deg, N_NODES / 4);
    count_deg_kernel<<<(E + T - 1) / T, T>>>(dst, deg, E);
    inv_deg_kernel<<<(N_NODES + T - 1) / T, T>>>(deg, N_NODES);

    // ---- SAGE layer 0: input x [N,128] ----
    gemm_dual<<<gemm_blocks, 256>>>(x, 128, 128, Wl0, Wr0, 128, P, R, N_NODES);
    zero_kernel<<<(N_NODES * 16 + T - 1) / T, T>>>((float4*)S, N_NODES * 16);
    scatter_kernel<<<(E * 4 + T - 1) / T, T>>>(P, src, dst, S, E);
    combine_kernel<<<(N_NODES * 16 + T - 1) / T, T>>>(S, R, deg, bl0, H, 0, N_NODES);

    // ---- SAGE layer 1: input H[:, 0:64] ----
    gemm_dual<<<gemm_blocks, 256>>>(H, 192, 64, Wl1, Wr1, 64, P, R, N_NODES);
    zero_kernel<<<(N_NODES * 16 + T - 1) / T, T>>>((float4*)S, N_NODES * 16);
    scatter_kernel<<<(E * 4 + T - 1) / T, T>>>(P, src, dst, S, E);
    combine_kernel<<<(N_NODES * 16 + T - 1) / T, T>>>(S, R, deg, bl1, H, 64, N_NODES);

    // ---- SAGE layer 2: input H[:, 64:128] ----
    gemm_dual<<<gemm_blocks, 256>>>(H + 64, 192, 64, Wl2, Wr2, 64, P, R, N_NODES);
    zero_kernel<<<(N_NODES * 16 + T - 1) / T, T>>>((float4*)S, N_NODES * 16);
    scatter_kernel<<<(E * 4 + T - 1) / T, T>>>(P, src, dst, S, E);
    combine_kernel<<<(N_NODES * 16 + T - 1) / T, T>>>(S, R, deg, bl2, H, 128, N_NODES);

    // ---- edge MLP decomposition: U = H @ Wm1[:, :192]^T, V = H @ Wm1[:, 192:]^T ----
    gemm_dual<<<gemm_blocks, 256>>>(H, 192, 192, Wm1, Wm1 + 192, 384, U, V, N_NODES);

    // ---- per-edge head ----
    edge_kernel<<<(E + T - 1) / T, T>>>(U, V, src, dst, bm1, Wm2, bm2, out, E);
}

// round 2
// speedup vs baseline: 1.4241x; 1.4241x over previous
#include <cuda_runtime.h>
#include <cstddef>

#define N_NODES 50000
#define SCAN_T 512
#define NSCAN_BLOCKS ((N_NODES + SCAN_T - 1) / SCAN_T)   // 98

// ---------------- scratch (device globals: no allocation allowed) ----------------
__device__ __align__(256) float g_P[N_NODES * 64];       // neighbor projection h @ Wl^T
__device__ __align__(256) float g_R[N_NODES * 64];       // root projection     h @ Wr^T
__device__ __align__(256) float g_H[N_NODES * 192];      // x_cat = [h0 | h1 | h2]
__device__ __align__(256) float g_U[N_NODES * 64];       // x_cat @ W1a^T
__device__ __align__(256) float g_V[N_NODES * 64];       // x_cat @ W1b^T
__device__ __align__(256) float g_deginv[N_NODES];
__device__ __align__(256) int   g_cnt[N_NODES];
__device__ __align__(256) int   g_off[N_NODES];
__device__ __align__(256) int   g_cur[N_NODES];
__device__ __align__(256) int   g_bsum[128];
__device__ __align__(256) int   g_adj[800000];           // src id per CSR slot

// ---------------- CSR build ----------------
__global__ void zero_int_kernel(int* __restrict__ p, int n) {
    int i = blockIdx.x * blockDim.x + threadIdx.x;
    if (i < n) p[i] = 0;
}

__global__ void count_deg_kernel(const int* __restrict__ dst, int* __restrict__ cnt, int E) {
    int e = blockIdx.x * blockDim.x + threadIdx.x;
    if (e < E) atomicAdd(&cnt[dst[e]], 1);
}

__global__ void scan1_kernel(const int* __restrict__ cnt, int* __restrict__ off,
                             int* __restrict__ bsum, int n) {
    __shared__ int sh[SCAN_T];
    int tid = threadIdx.x;
    int i = blockIdx.x * SCAN_T + tid;
    int v = (i < n) ? cnt[i] : 0;
    sh[tid] = v;
    __syncthreads();
#pragma unroll
    for (int d = 1; d < SCAN_T; d <<= 1) {
        int t = (tid >= d) ? sh[tid - d] : 0;
        __syncthreads();
        sh[tid] += t;
        __syncthreads();
    }
    if (i < n) off[i] = sh[tid] - v;       // exclusive (local)
    if (tid == SCAN_T - 1) bsum[blockIdx.x] = sh[tid];
}

__global__ void scan2_kernel(int* __restrict__ bsum, int nb) {
    __shared__ int sh[128];
    int tid = threadIdx.x;
    int v = (tid < nb) ? bsum[tid] : 0;
    sh[tid] = v;
    __syncthreads();
#pragma unroll
    for (int d = 1; d < 128; d <<= 1) {
        int t = (tid >= d) ? sh[tid - d] : 0;
        __syncthreads();
        sh[tid] += t;
        __syncthreads();
    }
    if (tid < nb) bsum[tid] = sh[tid] - v;  // exclusive
}

__global__ void scan3_kernel(int* __restrict__ off, int* __restrict__ cur,
                             const int* __restrict__ cnt, const int* __restrict__ bsum,
                             float* __restrict__ deginv, int n) {
    int i = blockIdx.x * blockDim.x + threadIdx.x;
    if (i >= n) return;
    int o = off[i] + bsum[i / SCAN_T];
    off[i] = o;
    cur[i] = o;
    deginv[i] = 1.0f / fmaxf((float)cnt[i], 1.0f);
}

__global__ void fill_kernel(const int* __restrict__ src, const int* __restrict__ dst,
                            int* __restrict__ cur, int* __restrict__ adj, int E) {
    int e = blockIdx.x * blockDim.x + threadIdx.x;
    if (e >= E) return;
    int d = dst[e];
    int pos = atomicAdd(&cur[d], 1);
    adj[pos] = src[e];
}

// ---------------- dual-output GEMM, double-buffered ----------------
// Ot[n, 0:64] = A[n, :K] @ Wt^T ; Ob[n, 0:64] = A[n, :K] @ Wb^T
// 64-node tile x 128 outs, BK=16, 256 threads, 4x8 per thread.
#define BK 16
__global__ __launch_bounds__(256) void gemm_dual(
    const float* __restrict__ A, int lda, int K,
    const float* __restrict__ Wt, const float* __restrict__ Wb, int wld,
    float* __restrict__ Ot, float* __restrict__ Ob, int nNodes)
{
    __shared__ float Ash[2][BK][68];
    __shared__ float Wsh[2][BK][132];

    const int t  = threadIdx.x;
    const int gi = t >> 4;              // node group 0..15  (4 nodes)
    const int gj = t & 15;              // out  group 0..15  (8 outs)
    const int n0 = blockIdx.x * 64;

    const int an = t >> 2, aq = t & 3;  // A loader: 1 float4 per thread
    const int o0 = (t * 2) >> 2;        // W loader: 2 float4 per thread
    const int wq0 = (t * 2) & 3;
    const int o1 = (t * 2 + 1) >> 2;
    const int wq1 = (t * 2 + 1) & 3;
    const float* wr0 = (o0 < 64) ? (Wt + (size_t)o0 * wld) : (Wb + (size_t)(o0 - 64) * wld);
    const float* wr1 = (o1 < 64) ? (Wt + (size_t)o1 * wld) : (Wb + (size_t)(o1 - 64) * wld);
    const bool aValid = (n0 + an < nNodes);
    const float* arow = A + (size_t)(n0 + an) * lda + aq * 4;

    float acc[4][8];
#pragma unroll
    for (int i = 0; i < 4; i++)
#pragma unroll
        for (int j = 0; j < 8; j++) acc[i][j] = 0.f;

    const int ntiles = K / BK;
    float4 aPre, wPre0, wPre1;

    // prologue: load tile 0 into buffer 0
    aPre = aValid ? *(const float4*)(arow) : make_float4(0, 0, 0, 0);
    wPre0 = *(const float4*)(wr0 + wq0 * 4);
    wPre1 = *(const float4*)(wr1 + wq1 * 4);
    {
        Ash[0][aq * 4 + 0][an] = aPre.x; Ash[0][aq * 4 + 1][an] = aPre.y;
        Ash[0][aq * 4 + 2][an] = aPre.z; Ash[0][aq * 4 + 3][an] = aPre.w;
        Wsh[0][wq0 * 4 + 0][o0] = wPre0.x; Wsh[0][wq0 * 4 + 1][o0] = wPre0.y;
        Wsh[0][wq0 * 4 + 2][o0] = wPre0.z; Wsh[0][wq0 * 4 + 3][o0] = wPre0.w;
        Wsh[0][wq1 * 4 + 0][o1] = wPre1.x; Wsh[0][wq1 * 4 + 1][o1] = wPre1.y;
        Wsh[0][wq1 * 4 + 2][o1] = wPre1.z; Wsh[0][wq1 * 4 + 3][o1] = wPre1.w;
    }

    for (int tt = 0; tt < ntiles; tt++) {
        __syncthreads();
        const int cur = tt & 1;
        const bool more = (tt + 1 < ntiles);
        if (more) {
            int k0 = (tt + 1) * BK;
            aPre = aValid ? *(const float4*)(arow + k0) : make_float4(0, 0, 0, 0);
            wPre0 = *(const float4*)(wr0 + k0 + wq0 * 4);
            wPre1 = *(const float4*)(wr1 + k0 + wq1 * 4);
        }
#pragma unroll
        for (int k = 0; k < BK; k++) {
            const float4 a4 = *(const float4*)&Ash[cur][k][gi * 4];
            const float4 w0 = *(const float4*)&Wsh[cur][k][gj * 8];
            const float4 w1 = *(const float4*)&Wsh[cur][k][gj * 8 + 4];
            const float av[4] = {a4.x, a4.y, a4.z, a4.w};
            const float wv[8] = {w0.x, w0.y, w0.z, w0.w, w1.x, w1.y, w1.z, w1.w};
#pragma unroll
            for (int i = 0; i < 4; i++)
#pragma unroll
                for (int j = 0; j < 8; j++)
                    acc[i][j] += av[i] * wv[j];
        }
        if (more) {
            const int nxt = cur ^ 1;
            Ash[nxt][aq * 4 + 0][an] = aPre.x; Ash[nxt][aq * 4 + 1][an] = aPre.y;
            Ash[nxt][aq * 4 + 2][an] = aPre.z; Ash[nxt][aq * 4 + 3][an] = aPre.w;
            Wsh[nxt][wq0 * 4 + 0][o0] = wPre0.x; Wsh[nxt][wq0 * 4 + 1][o0] = wPre0.y;
            Wsh[nxt][wq0 * 4 + 2][o0] = wPre0.z; Wsh[nxt][wq0 * 4 + 3][o0] = wPre0.w;
            Wsh[nxt][wq1 * 4 + 0][o1] = wPre1.x; Wsh[nxt][wq1 * 4 + 1][o1] = wPre1.y;
            Wsh[nxt][wq1 * 4 + 2][o1] = wPre1.z; Wsh[nxt][wq1 * 4 + 3][o1] = wPre1.w;
        }
    }

    float* O = (gj < 8) ? Ot : Ob;
    const int o = (gj & 7) * 8;
#pragma unroll
    for (int i = 0; i < 4; i++) {
        int n = n0 + gi * 4 + i;
        if (n < nNodes) {
            *(float4*)(O + (size_t)n * 64 + o)     = make_float4(acc[i][0], acc[i][1], acc[i][2], acc[i][3]);
            *(float4*)(O + (size_t)n * 64 + o + 4) = make_float4(acc[i][4], acc[i][5], acc[i][6], acc[i][7]);
        }
    }
}

// ---------------- CSR gather + combine: h = relu(mean_agg(P) + bl + R) -> H band ----------------
__global__ __launch_bounds__(256) void gather_combine(
    const float* __restrict__ P, const int* __restrict__ adj,
    const int* __restrict__ off, const int* __restrict__ cnt,
    const float* __restrict__ deginv, const float* __restrict__ R,
    const float* __restrict__ bl, float* __restrict__ H, int col, int n)
{
    int tid = blockIdx.x * blockDim.x + threadIdx.x;
    int nn = tid >> 4;
    int q  = tid & 15;
    if (nn >= n) return;
    const int beg = __ldg(off + nn);
    const int c   = __ldg(cnt + nn);
    const float4* Pq = (const float4*)P + q;

    float4 acc = make_float4(0.f, 0.f, 0.f, 0.f);
    int s0 = (c > 0) ? __ldg(adj + beg) : 0;
    for (int j = 0; j < c; j++) {
        int s1 = (j + 1 < c) ? __ldg(adj + beg + j + 1) : 0;
        float4 v = __ldg(Pq + (size_t)s0 * 16);
        acc.x += v.x; acc.y += v.y; acc.z += v.z; acc.w += v.w;
        s0 = s1;
    }
    const float di = __ldg(deginv + nn);
    const float4 r = *(const float4*)(R + (size_t)nn * 64 + q * 4);
    const float4 b = *(const float4*)(bl + q * 4);
    float4 h;
    h.x = fmaxf(fmaf(acc.x, di, b.x) + r.x, 0.f);
    h.y = fmaxf(fmaf(acc.y, di, b.y) + r.y, 0.f);
    h.z = fmaxf(fmaf(acc.z, di, b.z) + r.z, 0.f);
    h.w = fmaxf(fmaf(acc.w, di, b.w) + r.w, 0.f);
    *(float4*)(H + (size_t)nn * 192 + col + q * 4) = h;
}

// ---------------- edge head: out[e] = relu(U[src] + V[dst] + bm1) . wm2 + bm2 ----------------
__global__ __launch_bounds__(256) void edge_kernel(
    const float* __restrict__ U, const float* __restrict__ V,
    const int* __restrict__ src, const int* __restrict__ dst,
    const float* __restrict__ bm1, const float* __restrict__ Wm2,
    const float* __restrict__ bm2, float* __restrict__ out, int E)
{
    __shared__ float bsh[64];
    __shared__ float wsh[64];
    int t = threadIdx.x;
    if (t < 64)       bsh[t]      = bm1[t];
    else if (t < 128) wsh[t - 64] = Wm2[t - 64];
    __syncthreads();

    int e = blockIdx.x * blockDim.x + t;
    if (e >= E) return;
    int s = __ldg(src + e);
    int d = __ldg(dst + e);
    const float4* up = (const float4*)(U + (size_t)s * 64);
    const float4* vp = (const float4*)(V + (size_t)d * 64);
    float acc = __ldg(bm2);
#pragma unroll 4
    for (int j = 0; j < 16; j++) {
        float4 u = __ldg(up + j);
        float4 v = __ldg(vp + j);
        float4 b = *(const float4*)&bsh[j * 4];
        float4 w = *(const float4*)&wsh[j * 4];
        acc += fmaxf(u.x + v.x + b.x, 0.f) * w.x;
        acc += fmaxf(u.y + v.y + b.y, 0.f) * w.y;
        acc += fmaxf(u.z + v.z + b.z, 0.f) * w.z;
        acc += fmaxf(u.w + v.w + b.w, 0.f) * w.w;
    }
    out[e] = acc;
}

// ---------------- host launcher ----------------
extern "C" void kernel_launch(void* const* d_in, const int* in_sizes, int n_in,
                              void* d_out, int out_size)
{
    const float* x   = (const float*)d_in[0];
    const int*   src = (const int*)d_in[1];
    const int*   dst = (const int*)d_in[2];
    const float* Wl0 = (const float*)d_in[3];
    const float* bl0 = (const float*)d_in[4];
    const float* Wr0 = (const float*)d_in[5];
    const float* Wl1 = (const float*)d_in[6];
    const float* bl1 = (const float*)d_in[7];
    const float* Wr1 = (const float*)d_in[8];
    const float* Wl2 = (const float*)d_in[9];
    const float* bl2 = (const float*)d_in[10];
    const float* Wr2 = (const float*)d_in[11];
    const float* Wm1 = (const float*)d_in[12];
    const float* bm1 = (const float*)d_in[13];
    const float* Wm2 = (const float*)d_in[14];
    const float* bm2 = (const float*)d_in[15];
    float* out = (float*)d_out;
    const int E = in_sizes[1];

    void* p;
    cudaGetSymbolAddress(&p, g_P);      float* P      = (float*)p;
    cudaGetSymbolAddress(&p, g_R);      float* R      = (float*)p;
    cudaGetSymbolAddress(&p, g_H);      float* H      = (float*)p;
    cudaGetSymbolAddress(&p, g_U);      float* U      = (float*)p;
    cudaGetSymbolAddress(&p, g_V);      float* V      = (float*)p;
    cudaGetSymbolAddress(&p, g_deginv); float* deginv = (float*)p;
    cudaGetSymbolAddress(&p, g_cnt);    int*   cnt    = (int*)p;
    cudaGetSymbolAddress(&p, g_off);    int*   off    = (int*)p;
    cudaGetSymbolAddress(&p, g_cur);    int*   cur    = (int*)p;
    cudaGetSymbolAddress(&p, g_bsum);   int*   bsum   = (int*)p;
    cudaGetSymbolAddress(&p, g_adj);    int*   adj    = (int*)p;

    const int T = 256;
    const int gemm_blocks = (N_NODES + 63) / 64;
    const int gc_blocks   = (N_NODES * 16 + T - 1) / T;

    // ---- CSR build ----
    zero_int_kernel<<<(N_NODES + T - 1) / T, T>>>(cnt, N_NODES);
    count_deg_kernel<<<(E + T - 1) / T, T>>>(dst, cnt, E);
    scan1_kernel<<<NSCAN_BLOCKS, SCAN_T>>>(cnt, off, bsum, N_NODES);
    scan2_kernel<<<1, 128>>>(bsum, NSCAN_BLOCKS);
    scan3_kernel<<<(N_NODES + T - 1) / T, T>>>(off, cur, cnt, bsum, deginv, N_NODES);
    fill_kernel<<<(E + T - 1) / T, T>>>(src, dst, cur, adj, E);

    // ---- SAGE layer 0: input x [N,128] ----
    gemm_dual<<<gemm_blocks, 256>>>(x, 128, 128, Wl0, Wr0, 128, P, R, N_NODES);
    gather_combine<<<gc_blocks, T>>>(P, adj, off, cnt, deginv, R, bl0, H, 0, N_NODES);

    // ---- SAGE layer 1: input H[:, 0:64] ----
    gemm_dual<<<gemm_blocks, 256>>>(H, 192, 64, Wl1, Wr1, 64, P, R, N_NODES);
    gather_combine<<<gc_blocks, T>>>(P, adj, off, cnt, deginv, R, bl1, H, 64, N_NODES);

    // ---- SAGE layer 2: input H[:, 64:128] ----
    gemm_dual<<<gemm_blocks, 256>>>(H + 64, 192, 64, Wl2, Wr2, 64, P, R, N_NODES);
    gather_combine<<<gc_blocks, T>>>(P, adj, off, cnt, deginv, R, bl2, H, 128, N_NODES);

    // ---- edge MLP decomposition: U = H @ Wm1[:, :192]^T, V = H @ Wm1[:, 192:]^T ----
    gemm_dual<<<gemm_blocks, 256>>>(H, 192, 192, Wm1, Wm1 + 192, 384, U, V, N_NODES);

    // ---- per-edge head ----
    edge_kernel<<<(E + T - 1) / T, T>>>(U, V, src, dst, bm1, Wm2, bm2, out, E);
}

// round 3
// speedup vs baseline: 1.7961x; 1.2612x over previous
#include <cuda_runtime.h>
#include <cstdint>
#include <cstddef>

#define N_NODES 50000
#define SCAN_T 512
#define NSCAN_BLOCKS ((N_NODES + SCAN_T - 1) / SCAN_T)   // 98

// ---------------- scratch (device globals: no allocation allowed) ----------------
__device__ __align__(256) float g_P[N_NODES * 64];
__device__ __align__(256) float g_R[N_NODES * 64];
__device__ __align__(256) float g_H[N_NODES * 192];
__device__ __align__(256) float g_U[N_NODES * 64];
__device__ __align__(256) float g_V[N_NODES * 64];
__device__ __align__(256) float g_deginv[N_NODES];
__device__ __align__(256) int   g_cnt[N_NODES];
__device__ __align__(256) int   g_off[N_NODES];
__device__ __align__(256) int   g_cur[N_NODES];
__device__ __align__(256) int   g_bsum[128];
__device__ __align__(256) int   g_adj[800000];

// ---------------- CSR build ----------------
__global__ void zero_int_kernel(int* __restrict__ p, int n) {
    int i = blockIdx.x * blockDim.x + threadIdx.x;
    if (i < n) p[i] = 0;
}

__global__ void count_deg_kernel(const int* __restrict__ dst, int* __restrict__ cnt, int E) {
    int e = blockIdx.x * blockDim.x + threadIdx.x;
    if (e < E) atomicAdd(&cnt[dst[e]], 1);
}

__global__ void scan1_kernel(const int* __restrict__ cnt, int* __restrict__ off,
                             int* __restrict__ bsum, int n) {
    __shared__ int sh[SCAN_T];
    int tid = threadIdx.x;
    int i = blockIdx.x * SCAN_T + tid;
    int v = (i < n) ? cnt[i] : 0;
    sh[tid] = v;
    __syncthreads();
#pragma unroll
    for (int d = 1; d < SCAN_T; d <<= 1) {
        int t = (tid >= d) ? sh[tid - d] : 0;
        __syncthreads();
        sh[tid] += t;
        __syncthreads();
    }
    if (i < n) off[i] = sh[tid] - v;
    if (tid == SCAN_T - 1) bsum[blockIdx.x] = sh[tid];
}

__global__ void scan2_kernel(int* __restrict__ bsum, int nb) {
    __shared__ int sh[128];
    int tid = threadIdx.x;
    int v = (tid < nb) ? bsum[tid] : 0;
    sh[tid] = v;
    __syncthreads();
#pragma unroll
    for (int d = 1; d < 128; d <<= 1) {
        int t = (tid >= d) ? sh[tid - d] : 0;
        __syncthreads();
        sh[tid] += t;
        __syncthreads();
    }
    if (tid < nb) bsum[tid] = sh[tid] - v;
}

__global__ void scan3_kernel(int* __restrict__ off, int* __restrict__ cur,
                             const int* __restrict__ cnt, const int* __restrict__ bsum,
                             float* __restrict__ deginv, int n) {
    int i = blockIdx.x * blockDim.x + threadIdx.x;
    if (i >= n) return;
    int o = off[i] + bsum[i / SCAN_T];
    off[i] = o;
    cur[i] = o;
    deginv[i] = 1.0f / fmaxf((float)cnt[i], 1.0f);
}

__global__ void fill_kernel(const int* __restrict__ src, const int* __restrict__ dst,
                            int* __restrict__ cur, int* __restrict__ adj, int E) {
    int e = blockIdx.x * blockDim.x + threadIdx.x;
    if (e >= E) return;
    int d = dst[e];
    int pos = atomicAdd(&cur[d], 1);
    adj[pos] = src[e];
}

// ---------------- tf32 helpers ----------------
__device__ __forceinline__ uint2 split_tf32(float x) {
    unsigned hi, lo;
    asm("cvt.rna.tf32.f32 %0, %1;" : "=r"(hi) : "f"(x));
    float r = x - __uint_as_float(hi);
    asm("cvt.rna.tf32.f32 %0, %1;" : "=r"(lo) : "f"(r));
    return make_uint2(hi, lo);
}

__device__ __forceinline__ void mma8(float* d, unsigned a0, unsigned a1,
                                     unsigned a2, unsigned a3,
                                     unsigned b0, unsigned b1) {
    asm volatile(
        "mma.sync.aligned.m16n8k8.row.col.f32.tf32.tf32.f32 "
        "{%0,%1,%2,%3}, {%4,%5,%6,%7}, {%8,%9}, {%0,%1,%2,%3};"
        : "+f"(d[0]), "+f"(d[1]), "+f"(d[2]), "+f"(d[3])
        : "r"(a0), "r"(a1), "r"(a2), "r"(a3), "r"(b0), "r"(b1));
}

// ---------------- tensor-core dual-output GEMM ----------------
// Ot[n,0:64] = A[n,:K] @ Wt^T ; Ob[n,0:64] = A[n,:K] @ Wb^T
// Block tile 128 nodes x 128 outs; 8 warps (4M x 2N); warp = 32x64 = 2x8 mma tiles.
// fp32 accuracy via 3-term tf32 split, computed once at smem-store time.
#define TBK 16
#define SROW 18                          // uint2 per smem row (16 + pad)
#define ATILE (128 * SROW)               // uint2 per buffer

__device__ __forceinline__ void stash(uint2* base, int row, int kq, float4 v) {
    uint2* p = base + row * SROW + kq * 4;
    p[0] = split_tf32(v.x);
    p[1] = split_tf32(v.y);
    p[2] = split_tf32(v.z);
    p[3] = split_tf32(v.w);
}

__global__ __launch_bounds__(256, 2) void gemm_dual_tc(
    const float* __restrict__ A, int lda, int K,
    const float* __restrict__ Wt, const float* __restrict__ Wb, int wld,
    float* __restrict__ Ot, float* __restrict__ Ob, int nNodes)
{
    extern __shared__ uint2 smem_u2[];
    uint2* Ash = smem_u2;                 // [2][128][SROW]
    uint2* Wsh = smem_u2 + 2 * ATILE;     // [2][128][SROW]

    const int t = threadIdx.x;
    const int lane = t & 31, warp = t >> 5;
    const int grp = lane >> 2, tig = lane & 3;
    const int warpM = warp >> 1, warpN = warp & 1;
    const int m0 = blockIdx.x * 128;

    // loader mapping: thread t loads rows lm & lm+64, float4 chunk lkq
    const int lm = t >> 2;
    const int lkq = t & 3;
    const int ar0 = min(m0 + lm, nNodes - 1);
    const int ar1 = min(m0 + lm + 64, nNodes - 1);
    const float* aptr0 = A + (size_t)ar0 * lda + lkq * 4;
    const float* aptr1 = A + (size_t)ar1 * lda + lkq * 4;
    const float* wptr0 = Wt + (size_t)lm * wld + lkq * 4;
    const float* wptr1 = Wb + (size_t)lm * wld + lkq * 4;

    float acc[2][8][4];
#pragma unroll
    for (int mt = 0; mt < 2; mt++)
#pragma unroll
        for (int nt = 0; nt < 8; nt++)
#pragma unroll
            for (int j = 0; j < 4; j++) acc[mt][nt][j] = 0.f;

    const int ntiles = K / TBK;

    float4 pa0 = *(const float4*)(aptr0);
    float4 pa1 = *(const float4*)(aptr1);
    float4 pw0 = *(const float4*)(wptr0);
    float4 pw1 = *(const float4*)(wptr1);
    stash(Ash, lm, lkq, pa0);
    stash(Ash, lm + 64, lkq, pa1);
    stash(Wsh, lm, lkq, pw0);
    stash(Wsh, lm + 64, lkq, pw1);
    __syncthreads();

    for (int tt = 0; tt < ntiles; tt++) {
        const int cur = tt & 1;
        const bool more = (tt + 1 < ntiles);
        if (more) {
            const int ko = (tt + 1) * TBK;
            pa0 = *(const float4*)(aptr0 + ko);
            pa1 = *(const float4*)(aptr1 + ko);
            pw0 = *(const float4*)(wptr0 + ko);
            pw1 = *(const float4*)(wptr1 + ko);
        }
        const uint2* Ab = Ash + cur * ATILE;
        const uint2* Wc = Wsh + cur * ATILE;
#pragma unroll
        for (int ks = 0; ks < 2; ks++) {
            const int kb = ks * 8;
            uint2 af[2][4];
#pragma unroll
            for (int mt = 0; mt < 2; mt++) {
                const uint2* ap = Ab + (warpM * 32 + mt * 16 + grp) * SROW + kb + tig;
                af[mt][0] = ap[0];
                af[mt][1] = ap[8 * SROW];
                af[mt][2] = ap[4];
                af[mt][3] = ap[8 * SROW + 4];
            }
#pragma unroll
            for (int nt = 0; nt < 8; nt++) {
                const uint2* wp = Wc + (warpN * 64 + nt * 8 + grp) * SROW + kb + tig;
                const uint2 b0 = wp[0];
                const uint2 b1 = wp[4];
#pragma unroll
                for (int mt = 0; mt < 2; mt++) {
                    mma8(acc[mt][nt], af[mt][0].x, af[mt][1].x, af[mt][2].x, af[mt][3].x, b0.x, b1.x);
                    mma8(acc[mt][nt], af[mt][0].x, af[mt][1].x, af[mt][2].x, af[mt][3].x, b0.y, b1.y);
                    mma8(acc[mt][nt], af[mt][0].y, af[mt][1].y, af[mt][2].y, af[mt][3].y, b0.x, b1.x);
                }
            }
        }
        if (more) {
            const int nxt = cur ^ 1;
            stash(Ash + nxt * ATILE, lm, lkq, pa0);
            stash(Ash + nxt * ATILE, lm + 64, lkq, pa1);
            stash(Wsh + nxt * ATILE, lm, lkq, pw0);
            stash(Wsh + nxt * ATILE, lm + 64, lkq, pw1);
        }
        __syncthreads();
    }

    float* O = warpN ? Ob : Ot;
#pragma unroll
    for (int mt = 0; mt < 2; mt++) {
#pragma unroll
        for (int nt = 0; nt < 8; nt++) {
            const int r0 = m0 + warpM * 32 + mt * 16 + grp;
            const int col = nt * 8 + tig * 2;
            if (r0 < nNodes)
                *(float2*)(O + (size_t)r0 * 64 + col) = make_float2(acc[mt][nt][0], acc[mt][nt][1]);
            const int r1 = r0 + 8;
            if (r1 < nNodes)
                *(float2*)(O + (size_t)r1 * 64 + col) = make_float2(acc[mt][nt][2], acc[mt][nt][3]);
        }
    }
}

#define GEMM_SMEM (4 * ATILE * (int)sizeof(uint2))   // 73728 bytes

// ---------------- CSR gather + combine ----------------
__global__ __launch_bounds__(256) void gather_combine(
    const float* __restrict__ P, const int* __restrict__ adj,
    const int* __restrict__ off, const int* __restrict__ cnt,
    const float* __restrict__ deginv, const float* __restrict__ R,
    const float* __restrict__ bl, float* __restrict__ H, int col, int n)
{
    int tid = blockIdx.x * blockDim.x + threadIdx.x;
    int nn = tid >> 4;
    int q  = tid & 15;
    if (nn >= n) return;
    const int beg = __ldg(off + nn);
    const int c   = __ldg(cnt + nn);
    const float4* Pq = (const float4*)P + q;

    float4 acc = make_float4(0.f, 0.f, 0.f, 0.f);
    int s0 = (c > 0) ? __ldg(adj + beg) : 0;
    for (int j = 0; j < c; j++) {
        int s1 = (j + 1 < c) ? __ldg(adj + beg + j + 1) : 0;
        float4 v = __ldg(Pq + (size_t)s0 * 16);
        acc.x += v.x; acc.y += v.y; acc.z += v.z; acc.w += v.w;
        s0 = s1;
    }
    const float di = __ldg(deginv + nn);
    const float4 r = *(const float4*)(R + (size_t)nn * 64 + q * 4);
    const float4 b = *(const float4*)(bl + q * 4);
    float4 h;
    h.x = fmaxf(fmaf(acc.x, di, b.x) + r.x, 0.f);
    h.y = fmaxf(fmaf(acc.y, di, b.y) + r.y, 0.f);
    h.z = fmaxf(fmaf(acc.z, di, b.z) + r.z, 0.f);
    h.w = fmaxf(fmaf(acc.w, di, b.w) + r.w, 0.f);
    *(float4*)(H + (size_t)nn * 192 + col + q * 4) = h;
}

// ---------------- edge head ----------------
__global__ __launch_bounds__(256) void edge_kernel(
    const float* __restrict__ U, const float* __restrict__ V,
    const int* __restrict__ src, const int* __restrict__ dst,
    const float* __restrict__ bm1, const float* __restrict__ Wm2,
    const float* __restrict__ bm2, float* __restrict__ out, int E)
{
    __shared__ float bsh[64];
    __shared__ float wsh[64];
    int t = threadIdx.x;
    if (t < 64)       bsh[t]      = bm1[t];
    else if (t < 128) wsh[t - 64] = Wm2[t - 64];
    __syncthreads();

    int e = blockIdx.x * blockDim.x + t;
    if (e >= E) return;
    int s = __ldg(src + e);
    int d = __ldg(dst + e);
    const float4* up = (const float4*)(U + (size_t)s * 64);
    const float4* vp = (const float4*)(V + (size_t)d * 64);
    float acc = __ldg(bm2);
#pragma unroll 4
    for (int j = 0; j < 16; j++) {
        float4 u = __ldg(up + j);
        float4 v = __ldg(vp + j);
        float4 b = *(const float4*)&bsh[j * 4];
        float4 w = *(const float4*)&wsh[j * 4];
        acc += fmaxf(u.x + v.x + b.x, 0.f) * w.x;
        acc += fmaxf(u.y + v.y + b.y, 0.f) * w.y;
        acc += fmaxf(u.z + v.z + b.z, 0.f) * w.z;
        acc += fmaxf(u.w + v.w + b.w, 0.f) * w.w;
    }
    out[e] = acc;
}

// ---------------- host launcher ----------------
extern "C" void kernel_launch(void* const* d_in, const int* in_sizes, int n_in,
                              void* d_out, int out_size)
{
    const float* x   = (const float*)d_in[0];
    const int*   src = (const int*)d_in[1];
    const int*   dst = (const int*)d_in[2];
    const float* Wl0 = (const float*)d_in[3];
    const float* bl0 = (const float*)d_in[4];
    const float* Wr0 = (const float*)d_in[5];
    const float* Wl1 = (const float*)d_in[6];
    const float* bl1 = (const float*)d_in[7];
    const float* Wr1 = (const float*)d_in[8];
    const float* Wl2 = (const float*)d_in[9];
    const float* bl2 = (const float*)d_in[10];
    const float* Wr2 = (const float*)d_in[11];
    const float* Wm1 = (const float*)d_in[12];
    const float* bm1 = (const float*)d_in[13];
    const float* Wm2 = (const float*)d_in[14];
    const float* bm2 = (const float*)d_in[15];
    float* out = (float*)d_out;
    const int E = in_sizes[1];

    void* p;
    cudaGetSymbolAddress(&p, g_P);      float* P      = (float*)p;
    cudaGetSymbolAddress(&p, g_R);      float* R      = (float*)p;
    cudaGetSymbolAddress(&p, g_H);      float* H      = (float*)p;
    cudaGetSymbolAddress(&p, g_U);      float* U      = (float*)p;
    cudaGetSymbolAddress(&p, g_V);      float* V      = (float*)p;
    cudaGetSymbolAddress(&p, g_deginv); float* deginv = (float*)p;
    cudaGetSymbolAddress(&p, g_cnt);    int*   cnt    = (int*)p;
    cudaGetSymbolAddress(&p, g_off);    int*   off    = (int*)p;
    cudaGetSymbolAddress(&p, g_cur);    int*   cur    = (int*)p;
    cudaGetSymbolAddress(&p, g_bsum);   int*   bsum   = (int*)p;
    cudaGetSymbolAddress(&p, g_adj);    int*   adj    = (int*)p;

    cudaFuncSetAttribute(gemm_dual_tc, cudaFuncAttributeMaxDynamicSharedMemorySize,
                         GEMM_SMEM);

    const int T = 256;
    const int gemm_blocks = (N_NODES + 127) / 128;       // 391
    const int gc_blocks   = (N_NODES * 16 + T - 1) / T;

    // ---- CSR build ----
    zero_int_kernel<<<(N_NODES + T - 1) / T, T>>>(cnt, N_NODES);
    count_deg_kernel<<<(E + T - 1) / T, T>>>(dst, cnt, E);
    scan1_kernel<<<NSCAN_BLOCKS, SCAN_T>>>(cnt, off, bsum, N_NODES);
    scan2_kernel<<<1, 128>>>(bsum, NSCAN_BLOCKS);
    scan3_kernel<<<(N_NODES + T - 1) / T, T>>>(off, cur, cnt, bsum, deginv, N_NODES);
    fill_kernel<<<(E + T - 1) / T, T>>>(src, dst, cur, adj, E);

    // ---- SAGE layer 0 ----
    gemm_dual_tc<<<gemm_blocks, 256, GEMM_SMEM>>>(x, 128, 128, Wl0, Wr0, 128, P, R, N_NODES);
    gather_combine<<<gc_blocks, T>>>(P, adj, off, cnt, deginv, R, bl0, H, 0, N_NODES);

    // ---- SAGE layer 1 ----
    gemm_dual_tc<<<gemm_blocks, 256, GEMM_SMEM>>>(H, 192, 64, Wl1, Wr1, 64, P, R, N_NODES);
    gather_combine<<<gc_blocks, T>>>(P, adj, off, cnt, deginv, R, bl1, H, 64, N_NODES);

    // ---- SAGE layer 2 ----
    gemm_dual_tc<<<gemm_blocks, 256, GEMM_SMEM>>>(H + 64, 192, 64, Wl2, Wr2, 64, P, R, N_NODES);
    gather_combine<<<gc_blocks, T>>>(P, adj, off, cnt, deginv, R, bl2, H, 128, N_NODES);

    // ---- edge MLP decomposition ----
    gemm_dual_tc<<<gemm_blocks, 256, GEMM_SMEM>>>(H, 192, 192, Wm1, Wm1 + 192, 384, U, V, N_NODES);

    // ---- per-edge head ----
    edge_kernel<<<(E + T - 1) / T, T>>>(U, V, src, dst, bm1, Wm2, bm2, out, E);
}